// round 3
// baseline (speedup 1.0000x reference)
#include <cuda_runtime.h>

// Problem shapes (fixed by setup_inputs)
#define BB 64
#define TT 1024
#define JJ 32

// Scratch: per-(b,t) root trajectory, padded to float4 for vector loads. 4 MB.
__device__ float4 d_traj[BB * TT];

// Rotate point p by unit quaternion q=(w,x,y,z): p' = p + w*t + u×t, t = 2*(u×p)
__device__ __forceinline__ void qrotate(float w, float x, float y, float z,
                                        float px, float py, float pz,
                                        float& ox, float& oy, float& oz) {
    float tx = 2.0f * (y * pz - z * py);
    float ty = 2.0f * (z * px - x * pz);
    float tz = 2.0f * (x * py - y * px);
    ox = px + w * tx + (y * tz - z * ty);
    oy = py + w * ty + (z * tx - x * tz);
    oz = pz + w * tz + (x * ty - y * tx);
}

// Kernel 1: per-batch inclusive scan of e[t] = rot(inv[t-1], vel[t-1, joint0]),
// e[0]=0, plus base = rot(inv[0], pos[0, joint0]). Shfl warp scan + smem warp sums.
__global__ void __launch_bounds__(1024)
traj_scan_kernel(const float* __restrict__ glb_pos,
                 const float* __restrict__ glb_vel,
                 const float* __restrict__ root) {
    __shared__ float swx[32], swy[32], swz[32];
    int b = blockIdx.x;
    int t = threadIdx.x;          // 0..1023
    int lane = t & 31;
    int warp = t >> 5;

    float vx = 0.0f, vy = 0.0f, vz = 0.0f;
    if (t >= 1) {
        int s = t - 1;
        const float4 q = __ldg((const float4*)(root + (size_t)(b * TT + s) * 4));
        const float* v = glb_vel + ((size_t)(b * (TT - 1) + s) * JJ) * 3;  // joint 0
        qrotate(q.x, -q.y, -q.z, -q.w, __ldg(v), __ldg(v + 1), __ldg(v + 2), vx, vy, vz);
    }

    // warp-inclusive scan (3 components)
    #pragma unroll
    for (int d = 1; d < 32; d <<= 1) {
        float nx = __shfl_up_sync(0xffffffffu, vx, d);
        float ny = __shfl_up_sync(0xffffffffu, vy, d);
        float nz = __shfl_up_sync(0xffffffffu, vz, d);
        if (lane >= d) { vx += nx; vy += ny; vz += nz; }
    }
    if (lane == 31) { swx[warp] = vx; swy[warp] = vy; swz[warp] = vz; }
    __syncthreads();

    // warp 0 turns warp totals into exclusive prefixes
    if (warp == 0) {
        float ax = swx[lane], ay = swy[lane], az = swz[lane];
        float ix = ax, iy = ay, iz = az;
        #pragma unroll
        for (int d = 1; d < 32; d <<= 1) {
            float nx = __shfl_up_sync(0xffffffffu, ix, d);
            float ny = __shfl_up_sync(0xffffffffu, iy, d);
            float nz = __shfl_up_sync(0xffffffffu, iz, d);
            if (lane >= d) { ix += nx; iy += ny; iz += nz; }
        }
        swx[lane] = ix - ax; swy[lane] = iy - ay; swz[lane] = iz - az;
    }
    __syncthreads();

    // base = rotate(inv[b,0], glb_pos[b,0,joint0])
    const float4 q0 = __ldg((const float4*)(root + (size_t)b * TT * 4));
    const float* p0 = glb_pos + ((size_t)b * TT * JJ) * 3;
    float px, py, pz;
    qrotate(q0.x, -q0.y, -q0.z, -q0.w, __ldg(p0), __ldg(p0 + 1), __ldg(p0 + 2), px, py, pz);

    d_traj[b * TT + t] = make_float4(px + swx[warp] + vx,
                                     py + swy[warp] + vy,
                                     pz + swz[warp] + vz, 0.0f);
}

// Kernel 2: elementwise over (b,t,j), 4 joints per thread, all float4 traffic.
// Grid is exact (NT4 % 256 == 0), so no bounds check.
__global__ void __launch_bounds__(256)
main_kernel(const float* __restrict__ glb_pos,
            const float* __restrict__ glb_rot,
            const float* __restrict__ root,
            float* __restrict__ out) {
    int gid = blockIdx.x * blockDim.x + threadIdx.x;
    int e0 = gid << 2;          // first of 4 consecutive joints, same (b,t)
    int pair = gid >> 3;        // (b*T + t)  since J == 32 -> 8 threads per pair

    // inv root quaternion (same for all 4 joints)
    const float4 q = __ldg((const float4*)(root + (size_t)pair * 4));
    const float w = q.x, x = -q.y, y = -q.z, z = -q.w;

    // trajectory (x,z only)
    const float4 tr = __ldg(&d_traj[pair]);

    // --- position path: 12 floats = 3 float4 loads ---
    const float4* pp = (const float4*)(glb_pos + (size_t)e0 * 3);
    float4 pA = __ldg(pp), pB = __ldg(pp + 1), pC = __ldg(pp + 2);

    float ox0, oy0, oz0, ox1, oy1, oz1, ox2, oy2, oz2, ox3, oy3, oz3;
    qrotate(w, x, y, z, pA.x, pA.y, pA.z, ox0, oy0, oz0);
    qrotate(w, x, y, z, pA.w, pB.x, pB.y, ox1, oy1, oz1);
    qrotate(w, x, y, z, pB.z, pB.w, pC.x, ox2, oy2, oz2);
    qrotate(w, x, y, z, pC.y, pC.z, pC.w, ox3, oy3, oz3);

    ox0 += tr.x; oz0 += tr.z;
    ox1 += tr.x; oz1 += tr.z;
    ox2 += tr.x; oz2 += tr.z;
    ox3 += tr.x; oz3 += tr.z;

    float4* po = (float4*)(out + (size_t)e0 * 3);
    po[0] = make_float4(ox0, oy0, oz0, ox1);
    po[1] = make_float4(oy1, oz1, ox2, oy2);
    po[2] = make_float4(oz2, ox3, oy3, oz3);

    // --- rotation path: standardize(inv ⊗ glb_rot), 4 quats ---
    const float4* gp = (const float4*)(glb_rot + (size_t)e0 * 4);
    float4* ro = (float4*)(out + (size_t)BB * TT * JJ * 3 + (size_t)e0 * 4);
    #pragma unroll
    for (int j = 0; j < 4; j++) {
        float4 g = __ldg(gp + j);
        float rw = w * g.x - x * g.y - y * g.z - z * g.w;
        float rx = w * g.y + x * g.x + y * g.w - z * g.z;
        float ry = w * g.z - x * g.w + y * g.x + z * g.y;
        float rz = w * g.w + x * g.z - y * g.y + z * g.x;
        float s = (rw < 0.0f) ? -1.0f : 1.0f;
        ro[j] = make_float4(s * rw, s * rx, s * ry, s * rz);
    }
}

extern "C" void kernel_launch(void* const* d_in, const int* in_sizes, int n_in,
                              void* d_out, int out_size) {
    const float* glb_pos = (const float*)d_in[0];
    const float* glb_rot = (const float*)d_in[1];
    const float* glb_vel = (const float*)d_in[2];
    const float* root    = (const float*)d_in[3];
    float* out = (float*)d_out;

    traj_scan_kernel<<<BB, TT>>>(glb_pos, glb_vel, root);

    const int NT4 = BB * TT * JJ / 4;   // 524288, divisible by 256
    const int threads = 256;
    main_kernel<<<NT4 / threads, threads>>>(glb_pos, glb_rot, root, out);
}

// round 4
// speedup vs baseline: 1.0619x; 1.0619x over previous
#include <cuda_runtime.h>

// Problem shapes (fixed by setup_inputs)
#define BB 64
#define TT 1024
#define JJ 32

// Scratch: per-(b,t) root trajectory, padded to float4 for vector loads. 4 MB.
__device__ float4 d_traj[BB * TT];

// Rotate point p by unit quaternion q=(w,x,y,z): p' = p + w*t + u×t, t = 2*(u×p)
__device__ __forceinline__ void qrotate(float w, float x, float y, float z,
                                        float px, float py, float pz,
                                        float& ox, float& oy, float& oz) {
    float tx = 2.0f * (y * pz - z * py);
    float ty = 2.0f * (z * px - x * pz);
    float tz = 2.0f * (x * py - y * px);
    ox = px + w * tx + (y * tz - z * ty);
    oy = py + w * ty + (z * tx - x * tz);
    oz = pz + w * tz + (x * ty - y * tx);
}

// Kernel 1: per-batch inclusive scan of e[t] = rot(inv[t-1], vel[t-1, joint0]),
// plus base = rot(inv[0], pos[0, joint0]). Shfl warp scan + smem warp sums.
__global__ void __launch_bounds__(1024)
traj_scan_kernel(const float* __restrict__ glb_pos,
                 const float* __restrict__ glb_vel,
                 const float* __restrict__ root) {
    __shared__ float swx[32], swy[32], swz[32];
    int b = blockIdx.x;
    int t = threadIdx.x;          // 0..1023
    int lane = t & 31;
    int warp = t >> 5;

    float vx = 0.0f, vy = 0.0f, vz = 0.0f;
    if (t >= 1) {
        int s = t - 1;
        const float4 q = __ldg((const float4*)(root + (size_t)(b * TT + s) * 4));
        const float* v = glb_vel + ((size_t)(b * (TT - 1) + s) * JJ) * 3;  // joint 0
        qrotate(q.x, -q.y, -q.z, -q.w, __ldg(v), __ldg(v + 1), __ldg(v + 2), vx, vy, vz);
    }

    #pragma unroll
    for (int d = 1; d < 32; d <<= 1) {
        float nx = __shfl_up_sync(0xffffffffu, vx, d);
        float ny = __shfl_up_sync(0xffffffffu, vy, d);
        float nz = __shfl_up_sync(0xffffffffu, vz, d);
        if (lane >= d) { vx += nx; vy += ny; vz += nz; }
    }
    if (lane == 31) { swx[warp] = vx; swy[warp] = vy; swz[warp] = vz; }
    __syncthreads();

    if (warp == 0) {
        float ax = swx[lane], ay = swy[lane], az = swz[lane];
        float ix = ax, iy = ay, iz = az;
        #pragma unroll
        for (int d = 1; d < 32; d <<= 1) {
            float nx = __shfl_up_sync(0xffffffffu, ix, d);
            float ny = __shfl_up_sync(0xffffffffu, iy, d);
            float nz = __shfl_up_sync(0xffffffffu, iz, d);
            if (lane >= d) { ix += nx; iy += ny; iz += nz; }
        }
        swx[lane] = ix - ax; swy[lane] = iy - ay; swz[lane] = iz - az;
    }
    __syncthreads();

    const float4 q0 = __ldg((const float4*)(root + (size_t)b * TT * 4));
    const float* p0 = glb_pos + ((size_t)b * TT * JJ) * 3;
    float px, py, pz;
    qrotate(q0.x, -q0.y, -q0.z, -q0.w, __ldg(p0), __ldg(p0 + 1), __ldg(p0 + 2), px, py, pz);

    d_traj[b * TT + t] = make_float4(px + swx[warp] + vx,
                                     py + swy[warp] + vy,
                                     pz + swz[warp] + vz, 0.0f);
}

// Kernel 2: 256 threads per block, 1024 elements per block (4 per thread).
// Pos path staged through shared memory so all global traffic is coalesced
// LDG.128/STG.128. Rot path warp-strided (inherently coalesced).
__global__ void __launch_bounds__(256)
main_kernel(const float* __restrict__ glb_pos,
            const float* __restrict__ glb_rot,
            const float* __restrict__ root,
            float* __restrict__ out) {
    __shared__ float4 s_in[768];    // 1024 elements * 3 floats = 768 float4
    __shared__ float4 s_out[768];

    const int t = threadIdx.x;                 // 0..255
    const int blockElemBase = blockIdx.x << 10;  // 1024 elements per block
    const int blockPairBase = blockIdx.x << 5;   // 32 (b,t)-pairs per block
    const int f4base = blockIdx.x * 768;         // pos float4 base index

    // --- stage pos input: 3 coalesced LDG.128 per thread ---
    const float4* pin = (const float4*)glb_pos;
    float4 a0 = __ldg(pin + f4base + t);
    float4 a1 = __ldg(pin + f4base + 256 + t);
    float4 a2 = __ldg(pin + f4base + 512 + t);

    // --- rot path (independent of smem), warp-strided, fully coalesced ---
    {
        const float4* gp = (const float4*)glb_rot;
        float4* ro = (float4*)(out + (size_t)BB * TT * JJ * 3);
        #pragma unroll
        for (int j = 0; j < 4; j++) {
            int e = blockElemBase + j * 256 + t;
            int pr = e >> 5;                       // warp-uniform
            const float4 q = __ldg((const float4*)(root + (size_t)pr * 4));
            const float w = q.x, x = -q.y, y = -q.z, z = -q.w;
            float4 g = __ldg(gp + e);
            float rw = w * g.x - x * g.y - y * g.z - z * g.w;
            float rx = w * g.y + x * g.x + y * g.w - z * g.z;
            float ry = w * g.z - x * g.w + y * g.x + z * g.y;
            float rz = w * g.w + x * g.z - y * g.y + z * g.x;
            float s = (rw < 0.0f) ? -1.0f : 1.0f;
            ro[e] = make_float4(s * rw, s * rx, s * ry, s * rz);
        }
    }

    // --- write staged pos to smem, sync ---
    s_in[t] = a0;
    s_in[256 + t] = a1;
    s_in[512 + t] = a2;
    __syncthreads();

    // --- per-thread: 4 consecutive elements (12 floats = 3 float4 from smem) ---
    {
        float4 pA = s_in[3 * t];
        float4 pB = s_in[3 * t + 1];
        float4 pC = s_in[3 * t + 2];

        int pr = blockPairBase + (t >> 3);   // 4 elems (4t..4t+3) share one pair
        const float4 q = __ldg((const float4*)(root + (size_t)pr * 4));
        const float w = q.x, x = -q.y, y = -q.z, z = -q.w;
        const float4 tr = __ldg(&d_traj[pr]);

        float ox0, oy0, oz0, ox1, oy1, oz1, ox2, oy2, oz2, ox3, oy3, oz3;
        qrotate(w, x, y, z, pA.x, pA.y, pA.z, ox0, oy0, oz0);
        qrotate(w, x, y, z, pA.w, pB.x, pB.y, ox1, oy1, oz1);
        qrotate(w, x, y, z, pB.z, pB.w, pC.x, ox2, oy2, oz2);
        qrotate(w, x, y, z, pC.y, pC.z, pC.w, ox3, oy3, oz3);

        ox0 += tr.x; oz0 += tr.z;
        ox1 += tr.x; oz1 += tr.z;
        ox2 += tr.x; oz2 += tr.z;
        ox3 += tr.x; oz3 += tr.z;

        s_out[3 * t]     = make_float4(ox0, oy0, oz0, ox1);
        s_out[3 * t + 1] = make_float4(oy1, oz1, ox2, oy2);
        s_out[3 * t + 2] = make_float4(oz2, ox3, oy3, oz3);
    }
    __syncthreads();

    // --- store pos output: 3 coalesced STG.128 per thread ---
    float4* pout = (float4*)out;
    pout[f4base + t]       = s_out[t];
    pout[f4base + 256 + t] = s_out[256 + t];
    pout[f4base + 512 + t] = s_out[512 + t];
}

extern "C" void kernel_launch(void* const* d_in, const int* in_sizes, int n_in,
                              void* d_out, int out_size) {
    const float* glb_pos = (const float*)d_in[0];
    const float* glb_rot = (const float*)d_in[1];
    const float* glb_vel = (const float*)d_in[2];
    const float* root    = (const float*)d_in[3];
    float* out = (float*)d_out;

    traj_scan_kernel<<<BB, TT>>>(glb_pos, glb_vel, root);

    const int total = BB * TT * JJ;      // 2,097,152 elements
    main_kernel<<<total / 1024, 256>>>(glb_pos, glb_rot, root, out);
}

// round 6
// speedup vs baseline: 1.0678x; 1.0056x over previous
#include <cuda_runtime.h>

// Problem shapes (fixed by setup_inputs)
#define BB 64
#define TT 1024
#define JJ 32

// Scratch: per-(b,t) root trajectory, padded to float4 for vector loads. 4 MB.
__device__ float4 d_traj[BB * TT];

// Rotate point p by unit quaternion q=(w,x,y,z): p' = p + w*t + u×t, t = 2*(u×p)
__device__ __forceinline__ void qrotate(float w, float x, float y, float z,
                                        float px, float py, float pz,
                                        float& ox, float& oy, float& oz) {
    float tx = 2.0f * (y * pz - z * py);
    float ty = 2.0f * (z * px - x * pz);
    float tz = 2.0f * (x * py - y * px);
    ox = px + w * tx + (y * tz - z * ty);
    oy = py + w * ty + (z * tx - x * tz);
    oz = pz + w * tz + (x * ty - y * tx);
}

// Kernel 1: per-batch inclusive scan of e[t] = rot(inv[t-1], vel[t-1, joint0]),
// plus base = rot(inv[0], pos[0, joint0]). Shfl warp scan + smem warp sums.
__global__ void __launch_bounds__(1024)
traj_scan_kernel(const float* __restrict__ glb_pos,
                 const float* __restrict__ glb_vel,
                 const float* __restrict__ root) {
    __shared__ float swx[32], swy[32], swz[32];
    int b = blockIdx.x;
    int t = threadIdx.x;          // 0..1023
    int lane = t & 31;
    int warp = t >> 5;

    float vx = 0.0f, vy = 0.0f, vz = 0.0f;
    if (t >= 1) {
        int s = t - 1;
        const float4 q = __ldg((const float4*)(root + (size_t)(b * TT + s) * 4));
        const float* v = glb_vel + ((size_t)(b * (TT - 1) + s) * JJ) * 3;  // joint 0
        qrotate(q.x, -q.y, -q.z, -q.w, __ldg(v), __ldg(v + 1), __ldg(v + 2), vx, vy, vz);
    }

    #pragma unroll
    for (int d = 1; d < 32; d <<= 1) {
        float nx = __shfl_up_sync(0xffffffffu, vx, d);
        float ny = __shfl_up_sync(0xffffffffu, vy, d);
        float nz = __shfl_up_sync(0xffffffffu, vz, d);
        if (lane >= d) { vx += nx; vy += ny; vz += nz; }
    }
    if (lane == 31) { swx[warp] = vx; swy[warp] = vy; swz[warp] = vz; }
    __syncthreads();

    if (warp == 0) {
        float ax = swx[lane], ay = swy[lane], az = swz[lane];
        float ix = ax, iy = ay, iz = az;
        #pragma unroll
        for (int d = 1; d < 32; d <<= 1) {
            float nx = __shfl_up_sync(0xffffffffu, ix, d);
            float ny = __shfl_up_sync(0xffffffffu, iy, d);
            float nz = __shfl_up_sync(0xffffffffu, iz, d);
            if (lane >= d) { ix += nx; iy += ny; iz += nz; }
        }
        swx[lane] = ix - ax; swy[lane] = iy - ay; swz[lane] = iz - az;
    }
    __syncthreads();

    const float4 q0 = __ldg((const float4*)(root + (size_t)b * TT * 4));
    const float* p0 = glb_pos + ((size_t)b * TT * JJ) * 3;
    float px, py, pz;
    qrotate(q0.x, -q0.y, -q0.z, -q0.w, __ldg(p0), __ldg(p0 + 1), __ldg(p0 + 2), px, py, pz);

    d_traj[b * TT + t] = make_float4(px + swx[warp] + vx,
                                     py + swy[warp] + vy,
                                     pz + swz[warp] + vz, 0.0f);
}

// Kernel 2: 256 threads per block, 1024 elements per block (4 per thread).
// Pos path staged through ONE shared buffer (12 KB) so all global traffic is
// coalesced LDG.128/STG.128 while occupancy stays high. Rot path warp-strided.
__global__ void __launch_bounds__(256)
main_kernel(const float* __restrict__ glb_pos,
            const float* __restrict__ glb_rot,
            const float* __restrict__ root,
            float* __restrict__ out) {
    __shared__ float4 s[768];    // 1024 elements * 3 floats = 768 float4 (12 KB)

    const int t = threadIdx.x;                   // 0..255
    const int blockElemBase = blockIdx.x << 10;  // 1024 elements per block
    const int blockPairBase = blockIdx.x << 5;   // 32 (b,t)-pairs per block
    const int f4base = blockIdx.x * 768;         // pos float4 base index

    // --- stage pos input: 3 coalesced LDG.128 per thread ---
    const float4* pin = (const float4*)glb_pos;
    float4 a0 = __ldg(pin + f4base + t);
    float4 a1 = __ldg(pin + f4base + 256 + t);
    float4 a2 = __ldg(pin + f4base + 512 + t);

    // --- rot path (independent of smem), warp-strided, fully coalesced ---
    {
        const float4* gp = (const float4*)glb_rot;
        float4* ro = (float4*)(out + (size_t)BB * TT * JJ * 3);
        #pragma unroll
        for (int j = 0; j < 4; j++) {
            int e = blockElemBase + j * 256 + t;
            int pr = e >> 5;                       // warp-uniform
            const float4 q = __ldg((const float4*)(root + (size_t)pr * 4));
            const float w = q.x, x = -q.y, y = -q.z, z = -q.w;
            float4 g = __ldg(gp + e);
            float rw = w * g.x - x * g.y - y * g.z - z * g.w;
            float rx = w * g.y + x * g.x + y * g.w - z * g.z;
            float ry = w * g.z - x * g.w + y * g.x + z * g.y;
            float rz = w * g.w + x * g.z - y * g.y + z * g.x;
            float sg = (rw < 0.0f) ? -1.0f : 1.0f;
            ro[e] = make_float4(sg * rw, sg * rx, sg * ry, sg * rz);
        }
    }

    // --- write staged pos to smem ---
    s[t] = a0;
    s[256 + t] = a1;
    s[512 + t] = a2;
    __syncthreads();

    // --- per-thread: 4 consecutive elements (12 floats = 3 float4 from smem) ---
    float4 pA = s[3 * t];
    float4 pB = s[3 * t + 1];
    float4 pC = s[3 * t + 2];

    int pr = blockPairBase + (t >> 3);   // 4 elems (4t..4t+3) share one pair
    const float4 q = __ldg((const float4*)(root + (size_t)pr * 4));
    const float w = q.x, x = -q.y, y = -q.z, z = -q.w;
    const float4 tr = __ldg(&d_traj[pr]);

    float ox0, oy0, oz0, ox1, oy1, oz1, ox2, oy2, oz2, ox3, oy3, oz3;
    qrotate(w, x, y, z, pA.x, pA.y, pA.z, ox0, oy0, oz0);
    qrotate(w, x, y, z, pA.w, pB.x, pB.y, ox1, oy1, oz1);
    qrotate(w, x, y, z, pB.z, pB.w, pC.x, ox2, oy2, oz2);
    qrotate(w, x, y, z, pC.y, pC.z, pC.w, ox3, oy3, oz3);

    ox0 += tr.x; oz0 += tr.z;
    ox1 += tr.x; oz1 += tr.z;
    ox2 += tr.x; oz2 += tr.z;
    ox3 += tr.x; oz3 += tr.z;

    __syncthreads();   // everyone done reading s before overwrite

    s[3 * t]     = make_float4(ox0, oy0, oz0, ox1);
    s[3 * t + 1] = make_float4(oy1, oz1, ox2, oy2);
    s[3 * t + 2] = make_float4(oz2, ox3, oy3, oz3);
    __syncthreads();

    // --- store pos output: 3 coalesced STG.128 per thread ---
    float4* pout = (float4*)out;
    pout[f4base + t]       = s[t];
    pout[f4base + 256 + t] = s[256 + t];
    pout[f4base + 512 + t] = s[512 + t];
}

extern "C" void kernel_launch(void* const* d_in, const int* in_sizes, int n_in,
                              void* d_out, int out_size) {
    const float* glb_pos = (const float*)d_in[0];
    const float* glb_rot = (const float*)d_in[1];
    const float* glb_vel = (const float*)d_in[2];
    const float* root    = (const float*)d_in[3];
    float* out = (float*)d_out;

    traj_scan_kernel<<<BB, TT>>>(glb_pos, glb_vel, root);

    const int total = BB * TT * JJ;      // 2,097,152 elements
    main_kernel<<<total / 1024, 256>>>(glb_pos, glb_rot, root, out);
}

// round 7
// speedup vs baseline: 1.0725x; 1.0045x over previous
#include <cuda_runtime.h>

// Problem shapes (fixed by setup_inputs)
#define BB 64
#define TT 1024
#define JJ 32

// Scratch: per-(b,t) root trajectory, padded to float4 for vector loads. 4 MB.
__device__ float4 d_traj[BB * TT];

// Rotate point p by unit quaternion q=(w,x,y,z): p' = p + w*t + u×t, t = 2*(u×p)
__device__ __forceinline__ void qrotate(float w, float x, float y, float z,
                                        float px, float py, float pz,
                                        float& ox, float& oy, float& oz) {
    float tx = 2.0f * (y * pz - z * py);
    float ty = 2.0f * (z * px - x * pz);
    float tz = 2.0f * (x * py - y * px);
    ox = px + w * tx + (y * tz - z * ty);
    oy = py + w * ty + (z * tx - x * tz);
    oz = pz + w * tz + (x * ty - y * tx);
}

// Kernel 1: per-batch inclusive scan of e[t] = rot(inv[t-1], vel[t-1, joint0]),
// plus base = rot(inv[0], pos[0, joint0]). Shfl warp scan + smem warp sums.
// Vel joint-0 gather done as a single LDG.128 per thread (base is 16B-aligned,
// stride 384 B; 4th lane of the float4 is joint1.x, ignored).
__global__ void __launch_bounds__(1024)
traj_scan_kernel(const float* __restrict__ glb_pos,
                 const float* __restrict__ glb_vel,
                 const float* __restrict__ root) {
    __shared__ float swx[32], swy[32], swz[32];
    int b = blockIdx.x;
    int t = threadIdx.x;          // 0..1023
    int lane = t & 31;
    int warp = t >> 5;

    float vx = 0.0f, vy = 0.0f, vz = 0.0f;
    if (t >= 1) {
        int s = t - 1;
        const float4 q = __ldg((const float4*)(root + (size_t)(b * TT + s) * 4));
        const float4 v = __ldg((const float4*)(glb_vel +
                               ((size_t)(b * (TT - 1) + s) * JJ) * 3));  // joint 0 (+pad)
        qrotate(q.x, -q.y, -q.z, -q.w, v.x, v.y, v.z, vx, vy, vz);
    }

    #pragma unroll
    for (int d = 1; d < 32; d <<= 1) {
        float nx = __shfl_up_sync(0xffffffffu, vx, d);
        float ny = __shfl_up_sync(0xffffffffu, vy, d);
        float nz = __shfl_up_sync(0xffffffffu, vz, d);
        if (lane >= d) { vx += nx; vy += ny; vz += nz; }
    }
    if (lane == 31) { swx[warp] = vx; swy[warp] = vy; swz[warp] = vz; }
    __syncthreads();

    if (warp == 0) {
        float ax = swx[lane], ay = swy[lane], az = swz[lane];
        float ix = ax, iy = ay, iz = az;
        #pragma unroll
        for (int d = 1; d < 32; d <<= 1) {
            float nx = __shfl_up_sync(0xffffffffu, ix, d);
            float ny = __shfl_up_sync(0xffffffffu, iy, d);
            float nz = __shfl_up_sync(0xffffffffu, iz, d);
            if (lane >= d) { ix += nx; iy += ny; iz += nz; }
        }
        swx[lane] = ix - ax; swy[lane] = iy - ay; swz[lane] = iz - az;
    }
    __syncthreads();

    const float4 q0 = __ldg((const float4*)(root + (size_t)b * TT * 4));
    const float4 p0 = __ldg((const float4*)(glb_pos + ((size_t)b * TT * JJ) * 3));
    float px, py, pz;
    qrotate(q0.x, -q0.y, -q0.z, -q0.w, p0.x, p0.y, p0.z, px, py, pz);

    d_traj[b * TT + t] = make_float4(px + swx[warp] + vx,
                                     py + swy[warp] + vy,
                                     pz + swz[warp] + vz, 0.0f);
}

// Kernel 2: barrier-free, 2 elements per thread, all loads issued up front
// for maximum memory-level parallelism. Pos traffic via LDG.64/STG.64
// (8B-aligned), rot via LDG.128/STG.128, root/traj warp-uniform broadcasts.
__global__ void __launch_bounds__(256)
main_kernel(const float* __restrict__ glb_pos,
            const float* __restrict__ glb_rot,
            const float* __restrict__ root,
            float* __restrict__ out) {
    const int g = blockIdx.x * blockDim.x + threadIdx.x;   // 0 .. total/2-1
    const int e0 = g << 1;                                 // even element; e0,e0+1 same pair
    const int pair = e0 >> 5;                              // (b*T + t), warp-uniform

    // ---- issue ALL loads first (independent) ----
    const float4 q = __ldg((const float4*)(root + (size_t)pair * 4));
    const float4 tr = __ldg(&d_traj[pair]);

    const float2* p2 = (const float2*)glb_pos;             // float2 index 3*g
    float2 pa = __ldg(p2 + 3 * (size_t)g);
    float2 pb = __ldg(p2 + 3 * (size_t)g + 1);
    float2 pc = __ldg(p2 + 3 * (size_t)g + 2);

    const float4* gp = (const float4*)glb_rot;
    float4 g0 = __ldg(gp + e0);
    float4 g1 = __ldg(gp + e0 + 1);

    const float w = q.x, x = -q.y, y = -q.z, z = -q.w;

    // ---- rot path: standardize(inv ⊗ glb_rot) ----
    float4* ro = (float4*)(out + (size_t)BB * TT * JJ * 3);
    {
        float rw = w * g0.x - x * g0.y - y * g0.z - z * g0.w;
        float rx = w * g0.y + x * g0.x + y * g0.w - z * g0.z;
        float ry = w * g0.z - x * g0.w + y * g0.x + z * g0.y;
        float rz = w * g0.w + x * g0.z - y * g0.y + z * g0.x;
        float s = (rw < 0.0f) ? -1.0f : 1.0f;
        ro[e0] = make_float4(s * rw, s * rx, s * ry, s * rz);
    }
    {
        float rw = w * g1.x - x * g1.y - y * g1.z - z * g1.w;
        float rx = w * g1.y + x * g1.x + y * g1.w - z * g1.z;
        float ry = w * g1.z - x * g1.w + y * g1.x + z * g1.y;
        float rz = w * g1.w + x * g1.z - y * g1.y + z * g1.x;
        float s = (rw < 0.0f) ? -1.0f : 1.0f;
        ro[e0 + 1] = make_float4(s * rw, s * rx, s * ry, s * rz);
    }

    // ---- pos path: rotate two points, add x/z trajectory ----
    // elem0 = (pa.x, pa.y, pb.x), elem1 = (pb.y, pc.x, pc.y)
    float ox0, oy0, oz0, ox1, oy1, oz1;
    qrotate(w, x, y, z, pa.x, pa.y, pb.x, ox0, oy0, oz0);
    qrotate(w, x, y, z, pb.y, pc.x, pc.y, ox1, oy1, oz1);

    float2* o2 = (float2*)out;
    o2[3 * (size_t)g]     = make_float2(ox0 + tr.x, oy0);
    o2[3 * (size_t)g + 1] = make_float2(oz0 + tr.z, ox1 + tr.x);
    o2[3 * (size_t)g + 2] = make_float2(oy1, oz1 + tr.z);
}

extern "C" void kernel_launch(void* const* d_in, const int* in_sizes, int n_in,
                              void* d_out, int out_size) {
    const float* glb_pos = (const float*)d_in[0];
    const float* glb_rot = (const float*)d_in[1];
    const float* glb_vel = (const float*)d_in[2];
    const float* root    = (const float*)d_in[3];
    float* out = (float*)d_out;

    traj_scan_kernel<<<BB, TT>>>(glb_pos, glb_vel, root);

    const int halfTotal = BB * TT * JJ / 2;   // 1,048,576 threads
    main_kernel<<<halfTotal / 256, 256>>>(glb_pos, glb_rot, root, out);
}